// round 15
// baseline (speedup 1.0000x reference)
#include <cuda_runtime.h>
#include <cuda_bf16.h>
#include <math_constants.h>
#include <cstdint>

// Shapes
#define NB   2
#define NSEQ 1024
#define NTOK 2048      // B*N
#define NH   16
#define HD   64
#define NPV  8
#define DVV  88        // 64 (v) + 24 (vp coords)
#define CATD 1536
#define KSPLIT 4

// Scratch (static device globals; no allocation allowed)
__device__ float g_s   [NTOK * 384];          // s, tf32 bits
__device__ float g_wq  [384 * 1024];          // weights, tf32 bits
__device__ float g_wkv [384 * 2048];
__device__ float g_wvp [384 * 384];
__device__ float g_wout[CATD * 384];
__device__ float g_vpout[NTOK * 384];         // vp projection (pre-rotation, fp32)
__device__ float g_q  [NB*NH*NSEQ*HD];        // tf32 bits, PAIR-PERMUTED, x 2*SCALE*log2e
__device__ float g_k  [NB*NH*NSEQ*HD];        // tf32 bits, PAIR-PERMUTED
__device__ __nv_bfloat16 g_vb[(size_t)NB*NH*DVV*NSEQ];  // V+vp bf16, transposed, j-PERMUTED
__device__ float g_cat [NTOK*CATD];           // tf32 bits
__device__ float g_opart[KSPLIT][NTOK*384];   // split-K partials for out GEMM

// ---------------------------------------------------------------------------
// Helpers
// ---------------------------------------------------------------------------
__device__ __forceinline__ uint32_t f2tf32(float f) {
    uint32_t u;
    asm("cvt.rna.tf32.f32 %0, %1;" : "=r"(u) : "f"(f));
    return u;
}
__device__ __forceinline__ float ex2f(float x) {
    float r;
    asm("ex2.approx.f32 %0, %1;" : "=f"(r) : "f"(x));
    return r;
}
__device__ __forceinline__ uint32_t pack_bf16(float lo, float hi) {
    __nv_bfloat162 t = __float22bfloat162_rn(make_float2(lo, hi));
    return *(uint32_t*)&t;
}
__device__ __forceinline__ void mma_tf32(float* c,
                                         uint32_t a0, uint32_t a1, uint32_t a2, uint32_t a3,
                                         uint32_t b0, uint32_t b1) {
    asm volatile(
        "mma.sync.aligned.m16n8k8.row.col.f32.tf32.tf32.f32 "
        "{%0,%1,%2,%3}, {%4,%5,%6,%7}, {%8,%9}, {%0,%1,%2,%3};"
        : "+f"(c[0]), "+f"(c[1]), "+f"(c[2]), "+f"(c[3])
        : "r"(a0), "r"(a1), "r"(a2), "r"(a3), "r"(b0), "r"(b1));
}
__device__ __forceinline__ void mma_bf16(float* c,
                                         uint32_t a0, uint32_t a1, uint32_t a2, uint32_t a3,
                                         uint32_t b0, uint32_t b1) {
    asm volatile(
        "mma.sync.aligned.m16n8k16.row.col.f32.bf16.bf16.f32 "
        "{%0,%1,%2,%3}, {%4,%5,%6,%7}, {%8,%9}, {%0,%1,%2,%3};"
        : "+f"(c[0]), "+f"(c[1]), "+f"(c[2]), "+f"(c[3])
        : "r"(a0), "r"(a1), "r"(a2), "r"(a3), "r"(b0), "r"(b1));
}
__device__ __forceinline__ void cp16(void* dst, const void* src) {
    uint32_t d = (uint32_t)__cvta_generic_to_shared(dst);
    asm volatile("cp.async.cg.shared.global [%0], [%1], 16;" :: "r"(d), "l"(src));
}
#define CP_COMMIT() asm volatile("cp.async.commit_group;" ::: "memory")
#define CP_WAIT1()  asm volatile("cp.async.wait_group 1;" ::: "memory")
#define CP_WAIT0()  asm volatile("cp.async.wait_group 0;" ::: "memory")

// Pair permutation for tf32 fragments: dim c stored at kpos(c) so the
// fragment pair (c, c+4) is adjacent.
__device__ __forceinline__ int kpos(int c) {
    return ((c >> 3) << 3) + ((c & 3) << 1) + ((c >> 2) & 1);
}
// j-permutation for bf16 k16 B-fragments: within each 16-block, slots
// (2t, 2t+1, 2t+8, 2t+9) map to 4t..4t+3 (one 8-byte load per thread).
__device__ __forceinline__ int jp(int j) {
    const int s = j & 15;
    return (j & ~15) + (((s & 7) >> 1) << 2) + (s & 1) + (((s >> 3) & 1) << 1);
}

// ---------------------------------------------------------------------------
// Prep: convert s + all weights to tf32 bits (one streaming kernel).
// ---------------------------------------------------------------------------
__global__ __launch_bounds__(256) void cvt_prep_kernel(
    const float* __restrict__ s,    const float* __restrict__ w_q,
    const float* __restrict__ w_kv, const float* __restrict__ w_vp,
    const float* __restrict__ w_out)
{
    const int i = blockIdx.x * 256 + threadIdx.x;
    const float* src; float* dst; int off;
    if (i < 196608)      { src = s;     dst = g_s;    off = i; }
    else if (i < 294912) { src = w_q;   dst = g_wq;   off = i - 196608; }
    else if (i < 491520) { src = w_kv;  dst = g_wkv;  off = i - 294912; }
    else if (i < 528384) { src = w_vp;  dst = g_wvp;  off = i - 491520; }
    else                 { src = w_out; dst = g_wout; off = i - 528384; }
    float4 v = *(const float4*)(src + ((size_t)off << 2));
    float4 o = make_float4(__uint_as_float(f2tf32(v.x)), __uint_as_float(f2tf32(v.y)),
                           __uint_as_float(f2tf32(v.z)), __uint_as_float(f2tf32(v.w)));
    *(float4*)(dst + ((size_t)off << 2)) = o;
}

// ---------------------------------------------------------------------------
// cp.async double-buffered tf32 mainloop (pre-converted inputs, raw frags).
// ---------------------------------------------------------------------------
template<int MT>
struct Tiles { float As[2][MT][20]; float Bs[2][16][136]; };

template<int MT>
__device__ __forceinline__ void gemm_mainloop(
    const float* __restrict__ A, int lda, const float* __restrict__ Bw,
    int K, int ldb, int m0, int n0,
    Tiles<MT>* t, float acc[MT / 32][4][4])
{
    const int tid = threadIdx.x;
    const int wid = tid >> 5, lane = tid & 31;
    const int wm = wid >> 2, wn = wid & 3;
    const int g = lane >> 2, tg = lane & 3;
    constexpr int RT = MT / 32;

#pragma unroll
    for (int mt = 0; mt < RT; mt++)
#pragma unroll
        for (int nt = 0; nt < 4; nt++)
#pragma unroll
            for (int i = 0; i < 4; i++) acc[mt][nt][i] = 0.f;

    const int nc = K >> 4;

    {
#pragma unroll
        for (int r = 0; r < MT / 64; r++) {
            const int idx = tid + (r << 8);
            const int rr = idx >> 2, cc = (idx & 3) << 2;
            cp16(&t->As[0][rr][cc], &A[(size_t)(m0 + rr) * lda + cc]);
        }
#pragma unroll
        for (int r = 0; r < 2; r++) {
            const int idx = tid + (r << 8);
            const int rr = idx >> 5, cc = (idx & 31) << 2;
            cp16(&t->Bs[0][rr][cc], &Bw[(size_t)rr * ldb + n0 + cc]);
        }
        CP_COMMIT();
    }

    for (int c = 0; c < nc; c++) {
        const int s = c & 1;
        if (c + 1 < nc) {
            const int k1 = (c + 1) << 4;
            const int s1 = s ^ 1;
#pragma unroll
            for (int r = 0; r < MT / 64; r++) {
                const int idx = tid + (r << 8);
                const int rr = idx >> 2, cc = (idx & 3) << 2;
                cp16(&t->As[s1][rr][cc], &A[(size_t)(m0 + rr) * lda + k1 + cc]);
            }
#pragma unroll
            for (int r = 0; r < 2; r++) {
                const int idx = tid + (r << 8);
                const int rr = idx >> 5, cc = (idx & 31) << 2;
                cp16(&t->Bs[s1][rr][cc], &Bw[(size_t)(k1 + rr) * ldb + n0 + cc]);
            }
            CP_COMMIT();
            CP_WAIT1();
        } else {
            CP_WAIT0();
        }
        __syncthreads();

#pragma unroll
        for (int ks = 0; ks < 2; ks++) {
            const int kc = (ks << 3) + tg;
            uint32_t af[RT][4];
#pragma unroll
            for (int mt = 0; mt < RT; mt++) {
                const int mr = wm * (MT / 2) + (mt << 4) + g;
                af[mt][0] = __float_as_uint(t->As[s][mr    ][kc    ]);
                af[mt][1] = __float_as_uint(t->As[s][mr + 8][kc    ]);
                af[mt][2] = __float_as_uint(t->As[s][mr    ][kc + 4]);
                af[mt][3] = __float_as_uint(t->As[s][mr + 8][kc + 4]);
            }
            uint32_t bf[4][2];
#pragma unroll
            for (int nt = 0; nt < 4; nt++) {
                const int bc = (wn << 5) + (nt << 3) + g;
                bf[nt][0] = __float_as_uint(t->Bs[s][kc    ][bc]);
                bf[nt][1] = __float_as_uint(t->Bs[s][kc + 4][bc]);
            }
#pragma unroll
            for (int mt = 0; mt < RT; mt++)
#pragma unroll
                for (int nt = 0; nt < 4; nt++)
                    mma_tf32(acc[mt][nt], af[mt][0], af[mt][1], af[mt][2], af[mt][3],
                             bf[nt][0], bf[nt][1]);
        }
        __syncthreads();
    }
}

// ---------------------------------------------------------------------------
// Fused projection GEMM. q (scaled by 2*SCALE*log2e) and k stored kpos-
// permuted; v bf16 transposed + j-permuted into g_vb; vp fp32 into g_vpout.
// ---------------------------------------------------------------------------
__global__ __launch_bounds__(256) void proj_gemm_kernel(
    const float* __restrict__ b_q, const float* __restrict__ b_kv,
    const float* __restrict__ b_vp)
{
    __shared__ Tiles<128> t;
    const int bx = blockIdx.x;
    const int m0 = blockIdx.y << 7;

    const float* Bw; const float* bias; int ldb, n0, region;
    if (bx < 8)       { Bw = g_wq;  bias = b_q;  ldb = 1024; n0 = bx << 7;        region = 0; }
    else if (bx < 24) { Bw = g_wkv; bias = b_kv; ldb = 2048; n0 = (bx - 8) << 7;  region = 1; }
    else              { Bw = g_wvp; bias = b_vp; ldb = 384;  n0 = (bx - 24) << 7; region = 2; }

    float acc[4][4][4];
    gemm_mainloop<128>(g_s, 384, Bw, 384, ldb, m0, n0, &t, acc);

    const int tid = threadIdx.x;
    const int wid = tid >> 5, lane = tid & 31;
    const int wm = wid >> 2, wn = wid & 3;
    const int g = lane >> 2, tg = lane & 3;
    // 2*sqrt(1/(3*64)) * log2(e)  (exp2-domain softmax)
    const float sc2 = 0.14433756729740645f * 1.4426950408889634f;

#pragma unroll
    for (int mt = 0; mt < 4; mt++) {
        const int row0 = m0 + (wm << 6) + (mt << 4) + g;
#pragma unroll
        for (int nt = 0; nt < 4; nt++) {
            const int col = n0 + (wn << 5) + (nt << 3) + (tg << 1);
            const float b0 = bias[col], b1 = bias[col + 1];
#pragma unroll
            for (int half = 0; half < 2; half++) {
                const int row = row0 + half * 8;
                float2 v = make_float2(acc[mt][nt][half * 2]     + b0,
                                       acc[mt][nt][half * 2 + 1] + b1);
                const int b = row >> 10, n = row & 1023;
                if (region == 0) {
                    const int h = col >> 6, c = col & 63;
                    float* q = g_q + (size_t)(((b * NH + h) * NSEQ) + n) * HD;
                    const int p0 = kpos(c);                 // kpos(c+1) == p0+2
                    q[p0]     = __uint_as_float(f2tf32(v.x * sc2));
                    q[p0 + 2] = __uint_as_float(f2tf32(v.y * sc2));
                } else if (region == 1) {
                    const int h = col >> 7, r = col & 127;
                    if (r < 64) {
                        float* k = g_k + (size_t)(((b * NH + h) * NSEQ) + n) * HD;
                        const int p0 = kpos(r);
                        k[p0]     = __uint_as_float(f2tf32(v.x));
                        k[p0 + 2] = __uint_as_float(f2tf32(v.y));
                    } else {
                        __nv_bfloat16* vb = g_vb +
                            ((size_t)((b * NH + h) * DVV + (r - 64)) * NSEQ) + jp(n);
                        vb[0]    = __float2bfloat16(v.x);
                        vb[NSEQ] = __float2bfloat16(v.y);
                    }
                } else {
                    *(float2*)&g_vpout[(size_t)row * 384 + col] = v;
                }
            }
        }
    }
}

// ---------------------------------------------------------------------------
// Output GEMM, split-K with MT=128 tiles: grid (3, 16, KSPLIT).
// ---------------------------------------------------------------------------
__global__ __launch_bounds__(256) void out_gemm_kernel()
{
    __shared__ Tiles<128> t;
    const int m0 = blockIdx.y << 7;
    const int n0 = blockIdx.x << 7;
    const int z  = blockIdx.z;
    const int koff = z * (CATD / KSPLIT);

    float acc[4][4][4];
    gemm_mainloop<128>(g_cat + koff, CATD, g_wout + (size_t)koff * 384,
                       CATD / KSPLIT, 384, m0, n0, &t, acc);

    const int tid = threadIdx.x;
    const int wid = tid >> 5, lane = tid & 31;
    const int wm = wid >> 2, wn = wid & 3;
    const int g = lane >> 2, tg = lane & 3;
    float* dst = g_opart[z];

#pragma unroll
    for (int mt = 0; mt < 4; mt++) {
        const int row = m0 + (wm << 6) + (mt << 4) + g;
#pragma unroll
        for (int nt = 0; nt < 4; nt++) {
            const int col = n0 + (wn << 5) + (nt << 3) + (tg << 1);
            *(float2*)&dst[(size_t)row * 384 + col] =
                make_float2(acc[mt][nt][0], acc[mt][nt][1]);
            *(float2*)&dst[(size_t)(row + 8) * 384 + col] =
                make_float2(acc[mt][nt][2], acc[mt][nt][3]);
        }
    }
}

__global__ __launch_bounds__(256) void out_reduce_kernel(
    const float* __restrict__ b_out, float* __restrict__ out)
{
    const int idx = blockIdx.x * 256 + threadIdx.x;
    const int col = (idx << 2) % 384;
    float4 r = *(const float4*)&b_out[col];
#pragma unroll
    for (int z = 0; z < KSPLIT; z++) {
        float4 p = *(const float4*)&g_opart[z][idx << 2];
        r.x += p.x; r.y += p.y; r.z += p.z; r.w += p.w;
    }
    *(float4*)&out[idx << 2] = r;
}

// ---------------------------------------------------------------------------
// vp rotation: global frame -> bf16 transposed (j-permuted) g_vb rows 64..87.
// ---------------------------------------------------------------------------
__global__ void vp_rearrange_kernel(const float* __restrict__ rot,
                                    const float* __restrict__ trans) {
    const int row = blockIdx.x;
    const int b = row >> 10, n = row & 1023;
    const int t = threadIdx.x;
    const float* pr = g_vpout + (size_t)row * 384;
    const float* R = rot + row * 9;
    const float* T = trans + row * 3;
    const float x = pr[t];
    const float y = pr[128 + t];
    const float z = pr[256 + t];
    const float gx = R[0]*x + R[1]*y + R[2]*z + T[0];
    const float gy = R[3]*x + R[4]*y + R[5]*z + T[1];
    const float gz = R[6]*x + R[7]*y + R[8]*z + T[2];
    const int h = t >> 3, pp = t & 7;
    __nv_bfloat16* vb = g_vb +
        ((size_t)((b * NH + h) * DVV + 64 + pp * 3) * NSEQ) + jp(n);
    vb[0]        = __float2bfloat16(gx);
    vb[NSEQ]     = __float2bfloat16(gy);
    vb[2 * NSEQ] = __float2bfloat16(gz);
}

// ---------------------------------------------------------------------------
// Flash attention: 64-j tiles, pair-permuted K (LDS.64 QK frags),
// j-permuted V (LDS.64 PV frags), exp2 softmax, bf16 PV, fused cat epilogue.
// ks[64][72] fp32 (72 words = 8 mod 32 -> conflict-free LDS.64);
// vsT[88][80] bf16 (40 words = 8 mod 32 -> conflict-free LDS.64).
// ---------------------------------------------------------------------------
#define KS_STRIDE 72
#define VT_STRIDE 80
#define TILEF (64 * KS_STRIDE + (DVV * VT_STRIDE) / 2)   // floats: 4608 + 3520
#define ATT_SMEM (2 * TILEF * 4)                          // 65024 bytes

__global__ __launch_bounds__(256, 2) void attn_mma_kernel(
    const float* __restrict__ mask, const float* __restrict__ rot,
    const float* __restrict__ trans)
{
    extern __shared__ float smem_dyn[];
    __shared__ float msk2[2][64];
    float (*sp)[25] = (float(*)[25])smem_dyn;      // epilogue alias

    const int b = blockIdx.z, h = blockIdx.y;
    const int i0 = blockIdx.x << 7;
    const int tid = threadIdx.x;
    const int wid = tid >> 5, lane = tid & 31;
    const int g = lane >> 2, tg = lane & 3;
    const int wrow = wid << 4;

    const float* qbase = g_q + (size_t)((b * NH + h) * NSEQ) * HD;
    const float* kbase = g_k + (size_t)((b * NH + h) * NSEQ) * HD;
    const __nv_bfloat16* vbbase = g_vb + (size_t)(b * NH + h) * DVV * NSEQ;

    // Q fragments: permuted layout -> (a0,a2) and (a1,a3) are float2 loads
    uint32_t qa[8][4];
    {
        const float* q0 = qbase + (size_t)(i0 + wrow + g) * HD;
        const float* q1 = qbase + (size_t)(i0 + wrow + g + 8) * HD;
#pragma unroll
        for (int kt = 0; kt < 8; kt++) {
            float2 t0 = *(const float2*)&q0[(kt << 3) + (tg << 1)];
            float2 t1 = *(const float2*)&q1[(kt << 3) + (tg << 1)];
            qa[kt][0] = __float_as_uint(t0.x);
            qa[kt][2] = __float_as_uint(t0.y);
            qa[kt][1] = __float_as_uint(t1.x);
            qa[kt][3] = __float_as_uint(t1.y);
        }
    }
    const float CLOG = 144269.50408889634f;   // 1e5 * log2(e)
    const float A0 = CLOG * mask[b * NSEQ + i0 + wrow + g];
    const float A1 = CLOG * mask[b * NSEQ + i0 + wrow + g + 8];

    float l0 = 0.f, l1 = 0.f;
    float acc[11][4];
#pragma unroll
    for (int nt = 0; nt < 11; nt++)
#pragma unroll
        for (int i = 0; i < 4; i++) acc[nt][i] = 0.f;

    auto stage_tile = [&](int j0, int s) {
        float* buf = smem_dyn + s * TILEF;
        float (*ksb)[KS_STRIDE] = (float(*)[KS_STRIDE])buf;
        uint16_t* vtb = (uint16_t*)(buf + 64 * KS_STRIDE);
#pragma unroll
        for (int r = 0; r < 4; r++) {                   // ks: 64 rows x 16 segs
            const int task = tid + (r << 8);
            const int rr = task >> 4, seg = task & 15;
            cp16(&ksb[rr][seg << 2], &kbase[(size_t)(j0 + rr) * HD + (seg << 2)]);
        }
#pragma unroll
        for (int r = 0; r < 2; r++) {                   // vsT: 88 rows x 8 segs
            const int task = tid + (r << 8);
            const int d = task >> 3, seg = task & 7;
            cp16(vtb + d * VT_STRIDE + (seg << 3),
                 vbbase + (size_t)d * NSEQ + j0 + (seg << 3));
        }
        if (tid < 192) {
            const int task = tid + 512;
            const int d = task >> 3, seg = task & 7;
            cp16(vtb + d * VT_STRIDE + (seg << 3),
                 vbbase + (size_t)d * NSEQ + j0 + (seg << 3));
        }
        if (tid < 16) cp16(&msk2[s][tid << 2], &mask[b * NSEQ + j0 + (tid << 2)]);
    };

    stage_tile(0, 0);
    CP_COMMIT();

    for (int jt = 0; jt < 16; jt++) {
        const int s = jt & 1;
        if (jt + 1 < 16) {
            stage_tile((jt + 1) << 6, s ^ 1);
            CP_COMMIT();
            CP_WAIT1();
        } else {
            CP_WAIT0();
        }
        __syncthreads();

        float* buf = smem_dyn + s * TILEF;
        float (*ks)[KS_STRIDE] = (float(*)[KS_STRIDE])buf;
        const uint16_t* vsT = (const uint16_t*)(buf + 64 * KS_STRIDE);
        const float* msk = msk2[s];

        // S' = (log2e * logits) via tf32 mma; B-frags as single LDS.64
        float sc[8][4];
#pragma unroll
        for (int nt = 0; nt < 8; nt++)
#pragma unroll
            for (int i = 0; i < 4; i++) sc[nt][i] = 0.f;
#pragma unroll
        for (int kt = 0; kt < 8; kt++) {
#pragma unroll
            for (int nt = 0; nt < 8; nt++) {
                float2 bb = *(const float2*)&ks[(nt << 3) + g][(kt << 3) + (tg << 1)];
                mma_tf32(sc[nt], qa[kt][0], qa[kt][1], qa[kt][2], qa[kt][3],
                         __float_as_uint(bb.x), __float_as_uint(bb.y));
            }
        }

        // p = 2^(sc + A*mc - C); row sums; p overwrites sc
        float ps0 = 0.f, ps1 = 0.f;
#pragma unroll
        for (int nt = 0; nt < 8; nt++) {
            const float mc0 = msk[(nt << 3) + (tg << 1)];
            const float mc1 = msk[(nt << 3) + (tg << 1) + 1];
            sc[nt][0] = ex2f(sc[nt][0] + A0 * mc0 - CLOG);
            sc[nt][1] = ex2f(sc[nt][1] + A0 * mc1 - CLOG);
            sc[nt][2] = ex2f(sc[nt][2] + A1 * mc0 - CLOG);
            sc[nt][3] = ex2f(sc[nt][3] + A1 * mc1 - CLOG);
            ps0 += sc[nt][0] + sc[nt][1];
            ps1 += sc[nt][2] + sc[nt][3];
        }
        ps0 += __shfl_xor_sync(0xffffffffu, ps0, 1);
        ps0 += __shfl_xor_sync(0xffffffffu, ps0, 2);
        ps1 += __shfl_xor_sync(0xffffffffu, ps1, 1);
        ps1 += __shfl_xor_sync(0xffffffffu, ps1, 2);
        l0 += ps0;
        l1 += ps1;

        // O += P * V : 4 k16-groups x 11 n-tiles; b0|b1 = one LDS.64
#pragma unroll
        for (int m = 0; m < 4; m++) {
            uint32_t a0 = pack_bf16(sc[2*m][0],     sc[2*m][1]);
            uint32_t a1 = pack_bf16(sc[2*m][2],     sc[2*m][3]);
            uint32_t a2 = pack_bf16(sc[2*m + 1][0], sc[2*m + 1][1]);
            uint32_t a3 = pack_bf16(sc[2*m + 1][2], sc[2*m + 1][3]);
#pragma unroll
            for (int nt = 0; nt < 11; nt++) {
                const int hoff = ((nt << 3) + g) * VT_STRIDE + (m << 4) + (tg << 2);
                uint2 bb = *(const uint2*)(vsT + hoff);
                mma_bf16(acc[nt], a0, a1, a2, a3, bb.x, bb.y);
            }
        }
        __syncthreads();
    }

    const float inv0 = 1.0f / l0;
    const float inv1 = 1.0f / l1;
    const int lr0 = wrow + g, lr1 = wrow + g + 8;

    // v dims (cols 0..63): straight to g_cat as tf32 bits
    {
        float* cr0 = g_cat + (size_t)(b * NSEQ + i0 + lr0) * CATD + h * 64;
        float* cr1 = g_cat + (size_t)(b * NSEQ + i0 + lr1) * CATD + h * 64;
#pragma unroll
        for (int nt = 0; nt < 8; nt++) {
            const int col = (nt << 3) + (tg << 1);
            *(float2*)&cr0[col] = make_float2(
                __uint_as_float(f2tf32(acc[nt][0] * inv0)),
                __uint_as_float(f2tf32(acc[nt][1] * inv0)));
            *(float2*)&cr1[col] = make_float2(
                __uint_as_float(f2tf32(acc[nt][2] * inv1)),
                __uint_as_float(f2tf32(acc[nt][3] * inv1)));
        }
    }
    // pt dims: stage normalized (fp32) into sp (aliases dead tile storage)
#pragma unroll
    for (int nt = 8; nt < 11; nt++) {
        const int c = ((nt - 8) << 3) + (tg << 1);
        sp[lr0][c]     = acc[nt][0] * inv0;
        sp[lr0][c + 1] = acc[nt][1] * inv0;
        sp[lr1][c]     = acc[nt][2] * inv1;
        sp[lr1][c + 1] = acc[nt][3] * inv1;
    }
    __syncthreads();

    for (int task = tid; task < 1024; task += 256) {
        const int lr = task >> 3, p2 = task & 7;
        const int grow = b * NSEQ + i0 + lr;
        const float* R = rot + (size_t)grow * 9;
        const float* T = trans + (size_t)grow * 3;
        const float dx = sp[lr][p2 * 3 + 0] - T[0];
        const float dy = sp[lr][p2 * 3 + 1] - T[1];
        const float dz = sp[lr][p2 * 3 + 2] - T[2];
        const float lx = R[0] * dx + R[3] * dy + R[6] * dz;
        const float ly = R[1] * dx + R[4] * dy + R[7] * dz;
        const float lz = R[2] * dx + R[5] * dy + R[8] * dz;
        float* cr = g_cat + (size_t)grow * CATD;
        const int pcol = h * 8 + p2;
        cr[1024 + pcol] = __uint_as_float(f2tf32(lx));
        cr[1152 + pcol] = __uint_as_float(f2tf32(ly));
        cr[1280 + pcol] = __uint_as_float(f2tf32(lz));
        cr[1408 + pcol] = __uint_as_float(f2tf32(sqrtf(lx*lx + ly*ly + lz*lz + 1e-8f)));
    }
}

// ---------------------------------------------------------------------------
extern "C" void kernel_launch(void* const* d_in, const int* in_sizes, int n_in,
                              void* d_out, int out_size) {
    const float* s     = (const float*)d_in[0];
    // d_in[1] = z : unused by the reference -> never read
    const float* rot   = (const float*)d_in[2];
    const float* trans = (const float*)d_in[3];
    const float* mask  = (const float*)d_in[4];
    const float* w_q   = (const float*)d_in[5];
    const float* b_q   = (const float*)d_in[6];
    const float* w_kv  = (const float*)d_in[7];
    const float* b_kv  = (const float*)d_in[8];
    const float* w_vp  = (const float*)d_in[9];
    const float* b_vp  = (const float*)d_in[10];
    const float* w_out = (const float*)d_in[11];
    const float* b_out = (const float*)d_in[12];
    float* out = (float*)d_out;

    cudaFuncSetAttribute(attn_mma_kernel,
                         cudaFuncAttributeMaxDynamicSharedMemorySize, ATT_SMEM);

    // Convert s + weights to tf32 bits (streaming)
    cvt_prep_kernel<<<2640, 256>>>(s, w_q, w_kv, w_vp, w_out);

    // Fused projections (q|kv|vp)
    proj_gemm_kernel<<<dim3(27, 16), 256>>>(b_q, b_kv, b_vp);

    // vp rotation to global frame (bf16 transposed, j-permuted output)
    vp_rearrange_kernel<<<NTOK, 128>>>(rot, trans);

    // Tensor-core flash attention with fused cat epilogue
    attn_mma_kernel<<<dim3(8, NH, NB), 256, ATT_SMEM>>>(mask, rot, trans);

    // Output projection: split-K partials (MT=128) + deterministic reduce
    out_gemm_kernel<<<dim3(3, 16, KSPLIT), 256>>>();
    out_reduce_kernel<<<NTOK * 384 / 4 / 256, 256>>>(b_out, out);
}

// round 16
// speedup vs baseline: 1.0262x; 1.0262x over previous
#include <cuda_runtime.h>
#include <cuda_bf16.h>
#include <math_constants.h>
#include <cstdint>

// Shapes
#define NB   2
#define NSEQ 1024
#define NTOK 2048      // B*N
#define NH   16
#define HD   64
#define NPV  8
#define DVV  88        // 64 (v) + 24 (vp coords)
#define CATD 1536
#define KSPLIT 4

// Scratch (static device globals; no allocation allowed)
__device__ float g_s   [NTOK * 384];          // s, tf32 bits
__device__ float g_wq  [384 * 1024];          // weights, tf32 bits
__device__ float g_wkv [384 * 2048];
__device__ float g_wvp [384 * 384];
__device__ float g_wout[CATD * 384];
__device__ float g_vpout[NTOK * 384];         // vp projection (pre-rotation, fp32)
__device__ float g_q  [NB*NH*NSEQ*HD];        // tf32 bits, PAIR-PERMUTED, x 2*SCALE*log2e
__device__ float g_k  [NB*NH*NSEQ*HD];        // tf32 bits, PAIR-PERMUTED
__device__ __nv_bfloat16 g_vb[(size_t)NB*NH*DVV*NSEQ];  // V+vp bf16, transposed, j-PERMUTED
__device__ float g_cat [NTOK*CATD];           // tf32 bits
__device__ float g_opart[KSPLIT][NTOK*384];   // split-K partials for out GEMM

// ---------------------------------------------------------------------------
// Helpers
// ---------------------------------------------------------------------------
__device__ __forceinline__ uint32_t f2tf32(float f) {
    uint32_t u;
    asm("cvt.rna.tf32.f32 %0, %1;" : "=r"(u) : "f"(f));
    return u;
}
__device__ __forceinline__ float ex2f(float x) {
    float r;
    asm("ex2.approx.f32 %0, %1;" : "=f"(r) : "f"(x));
    return r;
}
__device__ __forceinline__ uint32_t pack_bf16(float lo, float hi) {
    __nv_bfloat162 t = __float22bfloat162_rn(make_float2(lo, hi));
    return *(uint32_t*)&t;
}
__device__ __forceinline__ void mma_tf32(float* c,
                                         uint32_t a0, uint32_t a1, uint32_t a2, uint32_t a3,
                                         uint32_t b0, uint32_t b1) {
    asm volatile(
        "mma.sync.aligned.m16n8k8.row.col.f32.tf32.tf32.f32 "
        "{%0,%1,%2,%3}, {%4,%5,%6,%7}, {%8,%9}, {%0,%1,%2,%3};"
        : "+f"(c[0]), "+f"(c[1]), "+f"(c[2]), "+f"(c[3])
        : "r"(a0), "r"(a1), "r"(a2), "r"(a3), "r"(b0), "r"(b1));
}
__device__ __forceinline__ void mma_bf16(float* c,
                                         uint32_t a0, uint32_t a1, uint32_t a2, uint32_t a3,
                                         uint32_t b0, uint32_t b1) {
    asm volatile(
        "mma.sync.aligned.m16n8k16.row.col.f32.bf16.bf16.f32 "
        "{%0,%1,%2,%3}, {%4,%5,%6,%7}, {%8,%9}, {%0,%1,%2,%3};"
        : "+f"(c[0]), "+f"(c[1]), "+f"(c[2]), "+f"(c[3])
        : "r"(a0), "r"(a1), "r"(a2), "r"(a3), "r"(b0), "r"(b1));
}
__device__ __forceinline__ void cp16(void* dst, const void* src) {
    uint32_t d = (uint32_t)__cvta_generic_to_shared(dst);
    asm volatile("cp.async.cg.shared.global [%0], [%1], 16;" :: "r"(d), "l"(src));
}
#define CP_COMMIT() asm volatile("cp.async.commit_group;" ::: "memory")
#define CP_WAIT1()  asm volatile("cp.async.wait_group 1;" ::: "memory")
#define CP_WAIT0()  asm volatile("cp.async.wait_group 0;" ::: "memory")

// Pair permutation for tf32 fragments: dim c stored at kpos(c) so the
// fragment pair (c, c+4) is adjacent.
__device__ __forceinline__ int kpos(int c) {
    return ((c >> 3) << 3) + ((c & 3) << 1) + ((c >> 2) & 1);
}
// j-permutation for bf16 k16 B-fragments: within each 16-block, slots
// (2t, 2t+1, 2t+8, 2t+9) map to 4t..4t+3 (one 8-byte load per thread).
__device__ __forceinline__ int jp(int j) {
    const int s = j & 15;
    return (j & ~15) + (((s & 7) >> 1) << 2) + (s & 1) + (((s >> 3) & 1) << 1);
}

// ---------------------------------------------------------------------------
// Prep: convert s + all weights to tf32 bits (one streaming kernel).
// ---------------------------------------------------------------------------
__global__ __launch_bounds__(256) void cvt_prep_kernel(
    const float* __restrict__ s,    const float* __restrict__ w_q,
    const float* __restrict__ w_kv, const float* __restrict__ w_vp,
    const float* __restrict__ w_out)
{
    const int i = blockIdx.x * 256 + threadIdx.x;
    const float* src; float* dst; int off;
    if (i < 196608)      { src = s;     dst = g_s;    off = i; }
    else if (i < 294912) { src = w_q;   dst = g_wq;   off = i - 196608; }
    else if (i < 491520) { src = w_kv;  dst = g_wkv;  off = i - 294912; }
    else if (i < 528384) { src = w_vp;  dst = g_wvp;  off = i - 491520; }
    else                 { src = w_out; dst = g_wout; off = i - 528384; }
    float4 v = *(const float4*)(src + ((size_t)off << 2));
    float4 o = make_float4(__uint_as_float(f2tf32(v.x)), __uint_as_float(f2tf32(v.y)),
                           __uint_as_float(f2tf32(v.z)), __uint_as_float(f2tf32(v.w)));
    *(float4*)(dst + ((size_t)off << 2)) = o;
}

// ---------------------------------------------------------------------------
// cp.async double-buffered tf32 mainloop (pre-converted inputs, raw frags).
// ---------------------------------------------------------------------------
template<int MT>
struct Tiles { float As[2][MT][20]; float Bs[2][16][136]; };

template<int MT>
__device__ __forceinline__ void gemm_mainloop(
    const float* __restrict__ A, int lda, const float* __restrict__ Bw,
    int K, int ldb, int m0, int n0,
    Tiles<MT>* t, float acc[MT / 32][4][4])
{
    const int tid = threadIdx.x;
    const int wid = tid >> 5, lane = tid & 31;
    const int wm = wid >> 2, wn = wid & 3;
    const int g = lane >> 2, tg = lane & 3;
    constexpr int RT = MT / 32;

#pragma unroll
    for (int mt = 0; mt < RT; mt++)
#pragma unroll
        for (int nt = 0; nt < 4; nt++)
#pragma unroll
            for (int i = 0; i < 4; i++) acc[mt][nt][i] = 0.f;

    const int nc = K >> 4;

    {
#pragma unroll
        for (int r = 0; r < MT / 64; r++) {
            const int idx = tid + (r << 8);
            const int rr = idx >> 2, cc = (idx & 3) << 2;
            cp16(&t->As[0][rr][cc], &A[(size_t)(m0 + rr) * lda + cc]);
        }
#pragma unroll
        for (int r = 0; r < 2; r++) {
            const int idx = tid + (r << 8);
            const int rr = idx >> 5, cc = (idx & 31) << 2;
            cp16(&t->Bs[0][rr][cc], &Bw[(size_t)rr * ldb + n0 + cc]);
        }
        CP_COMMIT();
    }

    for (int c = 0; c < nc; c++) {
        const int s = c & 1;
        if (c + 1 < nc) {
            const int k1 = (c + 1) << 4;
            const int s1 = s ^ 1;
#pragma unroll
            for (int r = 0; r < MT / 64; r++) {
                const int idx = tid + (r << 8);
                const int rr = idx >> 2, cc = (idx & 3) << 2;
                cp16(&t->As[s1][rr][cc], &A[(size_t)(m0 + rr) * lda + k1 + cc]);
            }
#pragma unroll
            for (int r = 0; r < 2; r++) {
                const int idx = tid + (r << 8);
                const int rr = idx >> 5, cc = (idx & 31) << 2;
                cp16(&t->Bs[s1][rr][cc], &Bw[(size_t)(k1 + rr) * ldb + n0 + cc]);
            }
            CP_COMMIT();
            CP_WAIT1();
        } else {
            CP_WAIT0();
        }
        __syncthreads();

#pragma unroll
        for (int ks = 0; ks < 2; ks++) {
            const int kc = (ks << 3) + tg;
            uint32_t af[RT][4];
#pragma unroll
            for (int mt = 0; mt < RT; mt++) {
                const int mr = wm * (MT / 2) + (mt << 4) + g;
                af[mt][0] = __float_as_uint(t->As[s][mr    ][kc    ]);
                af[mt][1] = __float_as_uint(t->As[s][mr + 8][kc    ]);
                af[mt][2] = __float_as_uint(t->As[s][mr    ][kc + 4]);
                af[mt][3] = __float_as_uint(t->As[s][mr + 8][kc + 4]);
            }
            uint32_t bf[4][2];
#pragma unroll
            for (int nt = 0; nt < 4; nt++) {
                const int bc = (wn << 5) + (nt << 3) + g;
                bf[nt][0] = __float_as_uint(t->Bs[s][kc    ][bc]);
                bf[nt][1] = __float_as_uint(t->Bs[s][kc + 4][bc]);
            }
#pragma unroll
            for (int mt = 0; mt < RT; mt++)
#pragma unroll
                for (int nt = 0; nt < 4; nt++)
                    mma_tf32(acc[mt][nt], af[mt][0], af[mt][1], af[mt][2], af[mt][3],
                             bf[nt][0], bf[nt][1]);
        }
        __syncthreads();
    }
}

// ---------------------------------------------------------------------------
// Fused projection GEMM. q (scaled by 2*SCALE*log2e) and k stored kpos-
// permuted; v bf16 transposed + j-permuted into g_vb; vp fp32 into g_vpout.
// ---------------------------------------------------------------------------
__global__ __launch_bounds__(256) void proj_gemm_kernel(
    const float* __restrict__ b_q, const float* __restrict__ b_kv,
    const float* __restrict__ b_vp)
{
    __shared__ Tiles<128> t;
    const int bx = blockIdx.x;
    const int m0 = blockIdx.y << 7;

    const float* Bw; const float* bias; int ldb, n0, region;
    if (bx < 8)       { Bw = g_wq;  bias = b_q;  ldb = 1024; n0 = bx << 7;        region = 0; }
    else if (bx < 24) { Bw = g_wkv; bias = b_kv; ldb = 2048; n0 = (bx - 8) << 7;  region = 1; }
    else              { Bw = g_wvp; bias = b_vp; ldb = 384;  n0 = (bx - 24) << 7; region = 2; }

    float acc[4][4][4];
    gemm_mainloop<128>(g_s, 384, Bw, 384, ldb, m0, n0, &t, acc);

    const int tid = threadIdx.x;
    const int wid = tid >> 5, lane = tid & 31;
    const int wm = wid >> 2, wn = wid & 3;
    const int g = lane >> 2, tg = lane & 3;
    // 2*sqrt(1/(3*64)) * log2(e)  (exp2-domain softmax)
    const float sc2 = 0.14433756729740645f * 1.4426950408889634f;

#pragma unroll
    for (int mt = 0; mt < 4; mt++) {
        const int row0 = m0 + (wm << 6) + (mt << 4) + g;
#pragma unroll
        for (int nt = 0; nt < 4; nt++) {
            const int col = n0 + (wn << 5) + (nt << 3) + (tg << 1);
            const float b0 = bias[col], b1 = bias[col + 1];
#pragma unroll
            for (int half = 0; half < 2; half++) {
                const int row = row0 + half * 8;
                float2 v = make_float2(acc[mt][nt][half * 2]     + b0,
                                       acc[mt][nt][half * 2 + 1] + b1);
                const int b = row >> 10, n = row & 1023;
                if (region == 0) {
                    const int h = col >> 6, c = col & 63;
                    float* q = g_q + (size_t)(((b * NH + h) * NSEQ) + n) * HD;
                    const int p0 = kpos(c);                 // kpos(c+1) == p0+2
                    q[p0]     = __uint_as_float(f2tf32(v.x * sc2));
                    q[p0 + 2] = __uint_as_float(f2tf32(v.y * sc2));
                } else if (region == 1) {
                    const int h = col >> 7, r = col & 127;
                    if (r < 64) {
                        float* k = g_k + (size_t)(((b * NH + h) * NSEQ) + n) * HD;
                        const int p0 = kpos(r);
                        k[p0]     = __uint_as_float(f2tf32(v.x));
                        k[p0 + 2] = __uint_as_float(f2tf32(v.y));
                    } else {
                        __nv_bfloat16* vb = g_vb +
                            ((size_t)((b * NH + h) * DVV + (r - 64)) * NSEQ) + jp(n);
                        vb[0]    = __float2bfloat16(v.x);
                        vb[NSEQ] = __float2bfloat16(v.y);
                    }
                } else {
                    *(float2*)&g_vpout[(size_t)row * 384 + col] = v;
                }
            }
        }
    }
}

// ---------------------------------------------------------------------------
// Output GEMM, split-K with MT=64 tiles: grid (3, 32, KSPLIT) = 384 CTAs.
// (MT=128 retile measured SLOWER in R15 -- latency-bound, CTA count wins.)
// ---------------------------------------------------------------------------
__global__ __launch_bounds__(256) void out_gemm_kernel()
{
    __shared__ Tiles<64> t;
    const int m0 = blockIdx.y << 6;
    const int n0 = blockIdx.x << 7;
    const int z  = blockIdx.z;
    const int koff = z * (CATD / KSPLIT);

    float acc[2][4][4];
    gemm_mainloop<64>(g_cat + koff, CATD, g_wout + (size_t)koff * 384,
                      CATD / KSPLIT, 384, m0, n0, &t, acc);

    const int tid = threadIdx.x;
    const int wid = tid >> 5, lane = tid & 31;
    const int wm = wid >> 2, wn = wid & 3;
    const int g = lane >> 2, tg = lane & 3;
    float* dst = g_opart[z];

#pragma unroll
    for (int mt = 0; mt < 2; mt++) {
        const int row = m0 + (wm << 5) + (mt << 4) + g;
#pragma unroll
        for (int nt = 0; nt < 4; nt++) {
            const int col = n0 + (wn << 5) + (nt << 3) + (tg << 1);
            *(float2*)&dst[(size_t)row * 384 + col] =
                make_float2(acc[mt][nt][0], acc[mt][nt][1]);
            *(float2*)&dst[(size_t)(row + 8) * 384 + col] =
                make_float2(acc[mt][nt][2], acc[mt][nt][3]);
        }
    }
}

__global__ __launch_bounds__(256) void out_reduce_kernel(
    const float* __restrict__ b_out, float* __restrict__ out)
{
    const int idx = blockIdx.x * 256 + threadIdx.x;
    const int col = (idx << 2) % 384;
    float4 r = *(const float4*)&b_out[col];
#pragma unroll
    for (int z = 0; z < KSPLIT; z++) {
        float4 p = *(const float4*)&g_opart[z][idx << 2];
        r.x += p.x; r.y += p.y; r.z += p.z; r.w += p.w;
    }
    *(float4*)&out[idx << 2] = r;
}

// ---------------------------------------------------------------------------
// vp rotation: global frame -> bf16 transposed (j-permuted) g_vb rows 64..87.
// ---------------------------------------------------------------------------
__global__ void vp_rearrange_kernel(const float* __restrict__ rot,
                                    const float* __restrict__ trans) {
    const int row = blockIdx.x;
    const int b = row >> 10, n = row & 1023;
    const int t = threadIdx.x;
    const float* pr = g_vpout + (size_t)row * 384;
    const float* R = rot + row * 9;
    const float* T = trans + row * 3;
    const float x = pr[t];
    const float y = pr[128 + t];
    const float z = pr[256 + t];
    const float gx = R[0]*x + R[1]*y + R[2]*z + T[0];
    const float gy = R[3]*x + R[4]*y + R[5]*z + T[1];
    const float gz = R[6]*x + R[7]*y + R[8]*z + T[2];
    const int h = t >> 3, pp = t & 7;
    __nv_bfloat16* vb = g_vb +
        ((size_t)((b * NH + h) * DVV + 64 + pp * 3) * NSEQ) + jp(n);
    vb[0]        = __float2bfloat16(gx);
    vb[NSEQ]     = __float2bfloat16(gy);
    vb[2 * NSEQ] = __float2bfloat16(gz);
}

// ---------------------------------------------------------------------------
// Flash attention: 64-j tiles, pair-permuted K (LDS.64 QK frags),
// j-permuted V (LDS.64 PV frags), exp2 softmax, bf16 PV, fused cat epilogue.
// ks[64][72] fp32; vsT[88][80] bf16 (both strides conflict-free for LDS.64).
// ---------------------------------------------------------------------------
#define KS_STRIDE 72
#define VT_STRIDE 80
#define TILEF (64 * KS_STRIDE + (DVV * VT_STRIDE) / 2)   // floats: 4608 + 3520
#define ATT_SMEM (2 * TILEF * 4)                          // 65024 bytes

__global__ __launch_bounds__(256, 2) void attn_mma_kernel(
    const float* __restrict__ mask, const float* __restrict__ rot,
    const float* __restrict__ trans)
{
    extern __shared__ float smem_dyn[];
    __shared__ float msk2[2][64];
    float (*sp)[25] = (float(*)[25])smem_dyn;      // epilogue alias

    const int b = blockIdx.z, h = blockIdx.y;
    const int i0 = blockIdx.x << 7;
    const int tid = threadIdx.x;
    const int wid = tid >> 5, lane = tid & 31;
    const int g = lane >> 2, tg = lane & 3;
    const int wrow = wid << 4;

    const float* qbase = g_q + (size_t)((b * NH + h) * NSEQ) * HD;
    const float* kbase = g_k + (size_t)((b * NH + h) * NSEQ) * HD;
    const __nv_bfloat16* vbbase = g_vb + (size_t)(b * NH + h) * DVV * NSEQ;

    // Q fragments: permuted layout -> (a0,a2) and (a1,a3) are float2 loads
    uint32_t qa[8][4];
    {
        const float* q0 = qbase + (size_t)(i0 + wrow + g) * HD;
        const float* q1 = qbase + (size_t)(i0 + wrow + g + 8) * HD;
#pragma unroll
        for (int kt = 0; kt < 8; kt++) {
            float2 t0 = *(const float2*)&q0[(kt << 3) + (tg << 1)];
            float2 t1 = *(const float2*)&q1[(kt << 3) + (tg << 1)];
            qa[kt][0] = __float_as_uint(t0.x);
            qa[kt][2] = __float_as_uint(t0.y);
            qa[kt][1] = __float_as_uint(t1.x);
            qa[kt][3] = __float_as_uint(t1.y);
        }
    }
    const float CLOG = 144269.50408889634f;   // 1e5 * log2(e)
    const float A0 = CLOG * mask[b * NSEQ + i0 + wrow + g];
    const float A1 = CLOG * mask[b * NSEQ + i0 + wrow + g + 8];

    float l0 = 0.f, l1 = 0.f;
    float acc[11][4];
#pragma unroll
    for (int nt = 0; nt < 11; nt++)
#pragma unroll
        for (int i = 0; i < 4; i++) acc[nt][i] = 0.f;

    auto stage_tile = [&](int j0, int s) {
        float* buf = smem_dyn + s * TILEF;
        float (*ksb)[KS_STRIDE] = (float(*)[KS_STRIDE])buf;
        uint16_t* vtb = (uint16_t*)(buf + 64 * KS_STRIDE);
#pragma unroll
        for (int r = 0; r < 4; r++) {                   // ks: 64 rows x 16 segs
            const int task = tid + (r << 8);
            const int rr = task >> 4, seg = task & 15;
            cp16(&ksb[rr][seg << 2], &kbase[(size_t)(j0 + rr) * HD + (seg << 2)]);
        }
#pragma unroll
        for (int r = 0; r < 2; r++) {                   // vsT: 88 rows x 8 segs
            const int task = tid + (r << 8);
            const int d = task >> 3, seg = task & 7;
            cp16(vtb + d * VT_STRIDE + (seg << 3),
                 vbbase + (size_t)d * NSEQ + j0 + (seg << 3));
        }
        if (tid < 192) {
            const int task = tid + 512;
            const int d = task >> 3, seg = task & 7;
            cp16(vtb + d * VT_STRIDE + (seg << 3),
                 vbbase + (size_t)d * NSEQ + j0 + (seg << 3));
        }
        if (tid < 16) cp16(&msk2[s][tid << 2], &mask[b * NSEQ + j0 + (tid << 2)]);
    };

    stage_tile(0, 0);
    CP_COMMIT();

    for (int jt = 0; jt < 16; jt++) {
        const int s = jt & 1;
        if (jt + 1 < 16) {
            stage_tile((jt + 1) << 6, s ^ 1);
            CP_COMMIT();
            CP_WAIT1();
        } else {
            CP_WAIT0();
        }
        __syncthreads();

        float* buf = smem_dyn + s * TILEF;
        float (*ks)[KS_STRIDE] = (float(*)[KS_STRIDE])buf;
        const uint16_t* vsT = (const uint16_t*)(buf + 64 * KS_STRIDE);
        const float* msk = msk2[s];

        // S' = (log2e * logits) via tf32 mma; B-frags as single LDS.64
        float sc[8][4];
#pragma unroll
        for (int nt = 0; nt < 8; nt++)
#pragma unroll
            for (int i = 0; i < 4; i++) sc[nt][i] = 0.f;
#pragma unroll
        for (int kt = 0; kt < 8; kt++) {
#pragma unroll
            for (int nt = 0; nt < 8; nt++) {
                float2 bb = *(const float2*)&ks[(nt << 3) + g][(kt << 3) + (tg << 1)];
                mma_tf32(sc[nt], qa[kt][0], qa[kt][1], qa[kt][2], qa[kt][3],
                         __float_as_uint(bb.x), __float_as_uint(bb.y));
            }
        }

        // p = 2^(sc + A*mc - C); row sums; p overwrites sc
        float ps0 = 0.f, ps1 = 0.f;
#pragma unroll
        for (int nt = 0; nt < 8; nt++) {
            const float mc0 = msk[(nt << 3) + (tg << 1)];
            const float mc1 = msk[(nt << 3) + (tg << 1) + 1];
            sc[nt][0] = ex2f(sc[nt][0] + A0 * mc0 - CLOG);
            sc[nt][1] = ex2f(sc[nt][1] + A0 * mc1 - CLOG);
            sc[nt][2] = ex2f(sc[nt][2] + A1 * mc0 - CLOG);
            sc[nt][3] = ex2f(sc[nt][3] + A1 * mc1 - CLOG);
            ps0 += sc[nt][0] + sc[nt][1];
            ps1 += sc[nt][2] + sc[nt][3];
        }
        ps0 += __shfl_xor_sync(0xffffffffu, ps0, 1);
        ps0 += __shfl_xor_sync(0xffffffffu, ps0, 2);
        ps1 += __shfl_xor_sync(0xffffffffu, ps1, 1);
        ps1 += __shfl_xor_sync(0xffffffffu, ps1, 2);
        l0 += ps0;
        l1 += ps1;

        // O += P * V : 4 k16-groups x 11 n-tiles; b0|b1 = one LDS.64
#pragma unroll
        for (int m = 0; m < 4; m++) {
            uint32_t a0 = pack_bf16(sc[2*m][0],     sc[2*m][1]);
            uint32_t a1 = pack_bf16(sc[2*m][2],     sc[2*m][3]);
            uint32_t a2 = pack_bf16(sc[2*m + 1][0], sc[2*m + 1][1]);
            uint32_t a3 = pack_bf16(sc[2*m + 1][2], sc[2*m + 1][3]);
#pragma unroll
            for (int nt = 0; nt < 11; nt++) {
                const int hoff = ((nt << 3) + g) * VT_STRIDE + (m << 4) + (tg << 2);
                uint2 bb = *(const uint2*)(vsT + hoff);
                mma_bf16(acc[nt], a0, a1, a2, a3, bb.x, bb.y);
            }
        }
        __syncthreads();
    }

    const float inv0 = 1.0f / l0;
    const float inv1 = 1.0f / l1;
    const int lr0 = wrow + g, lr1 = wrow + g + 8;

    // v dims (cols 0..63): straight to g_cat as tf32 bits
    {
        float* cr0 = g_cat + (size_t)(b * NSEQ + i0 + lr0) * CATD + h * 64;
        float* cr1 = g_cat + (size_t)(b * NSEQ + i0 + lr1) * CATD + h * 64;
#pragma unroll
        for (int nt = 0; nt < 8; nt++) {
            const int col = (nt << 3) + (tg << 1);
            *(float2*)&cr0[col] = make_float2(
                __uint_as_float(f2tf32(acc[nt][0] * inv0)),
                __uint_as_float(f2tf32(acc[nt][1] * inv0)));
            *(float2*)&cr1[col] = make_float2(
                __uint_as_float(f2tf32(acc[nt][2] * inv1)),
                __uint_as_float(f2tf32(acc[nt][3] * inv1)));
        }
    }
    // pt dims: stage normalized (fp32) into sp (aliases dead tile storage)
#pragma unroll
    for (int nt = 8; nt < 11; nt++) {
        const int c = ((nt - 8) << 3) + (tg << 1);
        sp[lr0][c]     = acc[nt][0] * inv0;
        sp[lr0][c + 1] = acc[nt][1] * inv0;
        sp[lr1][c]     = acc[nt][2] * inv1;
        sp[lr1][c + 1] = acc[nt][3] * inv1;
    }
    __syncthreads();

    for (int task = tid; task < 1024; task += 256) {
        const int lr = task >> 3, p2 = task & 7;
        const int grow = b * NSEQ + i0 + lr;
        const float* R = rot + (size_t)grow * 9;
        const float* T = trans + (size_t)grow * 3;
        const float dx = sp[lr][p2 * 3 + 0] - T[0];
        const float dy = sp[lr][p2 * 3 + 1] - T[1];
        const float dz = sp[lr][p2 * 3 + 2] - T[2];
        const float lx = R[0] * dx + R[3] * dy + R[6] * dz;
        const float ly = R[1] * dx + R[4] * dy + R[7] * dz;
        const float lz = R[2] * dx + R[5] * dy + R[8] * dz;
        float* cr = g_cat + (size_t)grow * CATD;
        const int pcol = h * 8 + p2;
        cr[1024 + pcol] = __uint_as_float(f2tf32(lx));
        cr[1152 + pcol] = __uint_as_float(f2tf32(ly));
        cr[1280 + pcol] = __uint_as_float(f2tf32(lz));
        cr[1408 + pcol] = __uint_as_float(f2tf32(sqrtf(lx*lx + ly*ly + lz*lz + 1e-8f)));
    }
}

// ---------------------------------------------------------------------------
extern "C" void kernel_launch(void* const* d_in, const int* in_sizes, int n_in,
                              void* d_out, int out_size) {
    const float* s     = (const float*)d_in[0];
    // d_in[1] = z : unused by the reference -> never read
    const float* rot   = (const float*)d_in[2];
    const float* trans = (const float*)d_in[3];
    const float* mask  = (const float*)d_in[4];
    const float* w_q   = (const float*)d_in[5];
    const float* b_q   = (const float*)d_in[6];
    const float* w_kv  = (const float*)d_in[7];
    const float* b_kv  = (const float*)d_in[8];
    const float* w_vp  = (const float*)d_in[9];
    const float* b_vp  = (const float*)d_in[10];
    const float* w_out = (const float*)d_in[11];
    const float* b_out = (const float*)d_in[12];
    float* out = (float*)d_out;

    cudaFuncSetAttribute(attn_mma_kernel,
                         cudaFuncAttributeMaxDynamicSharedMemorySize, ATT_SMEM);

    // Convert s + weights to tf32 bits (streaming)
    cvt_prep_kernel<<<2640, 256>>>(s, w_q, w_kv, w_vp, w_out);

    // Fused projections (q|kv|vp)
    proj_gemm_kernel<<<dim3(27, 16), 256>>>(b_q, b_kv, b_vp);

    // vp rotation to global frame (bf16 transposed, j-permuted output)
    vp_rearrange_kernel<<<NTOK, 128>>>(rot, trans);

    // Tensor-core flash attention with fused cat epilogue
    attn_mma_kernel<<<dim3(8, NH, NB), 256, ATT_SMEM>>>(mask, rot, trans);

    // Output projection: split-K partials (MT=64, 384 CTAs) + reduce
    out_gemm_kernel<<<dim3(3, 32, KSPLIT), 256>>>();
    out_reduce_kernel<<<NTOK * 384 / 4 / 256, 256>>>(b_out, out);
}

// round 17
// speedup vs baseline: 1.0824x; 1.0548x over previous
#include <cuda_runtime.h>
#include <cuda_bf16.h>
#include <math_constants.h>
#include <cstdint>

// Shapes
#define NB   2
#define NSEQ 1024
#define NTOK 2048      // B*N
#define NH   16
#define HD   64
#define NPV  8
#define DVV  88        // 64 (v) + 24 (vp coords)
#define CATD 1536
#define KSPLIT 4

// Scratch (static device globals; no allocation allowed)
__device__ float g_s   [NTOK * 384];          // s, tf32 bits, kpos col-permuted
__device__ float g_wq  [384 * 1024];          // weights, tf32 bits (unpermuted)
__device__ float g_wkv [384 * 2048];
__device__ float g_wvp [384 * 384];
__device__ float g_wout[CATD * 384];
__device__ float g_vpout[NTOK * 384];         // vp projection (pre-rotation, fp32)
__device__ float g_q  [NB*NH*NSEQ*HD];        // tf32 bits, PAIR-PERMUTED, x 2*SCALE*log2e
__device__ float g_k  [NB*NH*NSEQ*HD];        // tf32 bits, PAIR-PERMUTED
__device__ __nv_bfloat16 g_vb[(size_t)NB*NH*DVV*NSEQ];  // V+vp bf16, transposed, j-PERMUTED
__device__ float g_cat [NTOK*CATD];           // tf32 bits, kpos col-permuted
__device__ float g_opart[KSPLIT][NTOK*384];   // split-K partials for out GEMM

// ---------------------------------------------------------------------------
// Helpers
// ---------------------------------------------------------------------------
__device__ __forceinline__ uint32_t f2tf32(float f) {
    uint32_t u;
    asm("cvt.rna.tf32.f32 %0, %1;" : "=r"(u) : "f"(f));
    return u;
}
__device__ __forceinline__ float ex2f(float x) {
    float r;
    asm("ex2.approx.f32 %0, %1;" : "=f"(r) : "f"(x));
    return r;
}
__device__ __forceinline__ uint32_t pack_bf16(float lo, float hi) {
    __nv_bfloat162 t = __float22bfloat162_rn(make_float2(lo, hi));
    return *(uint32_t*)&t;
}
__device__ __forceinline__ void mma_tf32(float* c,
                                         uint32_t a0, uint32_t a1, uint32_t a2, uint32_t a3,
                                         uint32_t b0, uint32_t b1) {
    asm volatile(
        "mma.sync.aligned.m16n8k8.row.col.f32.tf32.tf32.f32 "
        "{%0,%1,%2,%3}, {%4,%5,%6,%7}, {%8,%9}, {%0,%1,%2,%3};"
        : "+f"(c[0]), "+f"(c[1]), "+f"(c[2]), "+f"(c[3])
        : "r"(a0), "r"(a1), "r"(a2), "r"(a3), "r"(b0), "r"(b1));
}
__device__ __forceinline__ void mma_bf16(float* c,
                                         uint32_t a0, uint32_t a1, uint32_t a2, uint32_t a3,
                                         uint32_t b0, uint32_t b1) {
    asm volatile(
        "mma.sync.aligned.m16n8k16.row.col.f32.bf16.bf16.f32 "
        "{%0,%1,%2,%3}, {%4,%5,%6,%7}, {%8,%9}, {%0,%1,%2,%3};"
        : "+f"(c[0]), "+f"(c[1]), "+f"(c[2]), "+f"(c[3])
        : "r"(a0), "r"(a1), "r"(a2), "r"(a3), "r"(b0), "r"(b1));
}
__device__ __forceinline__ void cp16(void* dst, const void* src) {
    uint32_t d = (uint32_t)__cvta_generic_to_shared(dst);
    asm volatile("cp.async.cg.shared.global [%0], [%1], 16;" :: "r"(d), "l"(src));
}
#define CP_COMMIT() asm volatile("cp.async.commit_group;" ::: "memory")
#define CP_WAIT1()  asm volatile("cp.async.wait_group 1;" ::: "memory")
#define CP_WAIT0()  asm volatile("cp.async.wait_group 0;" ::: "memory")

// Pair permutation: logical dim c stored at kpos(c) so the tf32 fragment
// pair (c, c+4) is adjacent (one 64-bit access). Within-8 part:
__device__ __forceinline__ int kpos8(int l) { return ((l & 3) << 1) + (l >> 2); }
__device__ __forceinline__ int kpos(int c) { return (c & ~7) + kpos8(c & 7); }
// j-permutation for bf16 k16 B-fragments (V side).
__device__ __forceinline__ int jp(int j) {
    const int s = j & 15;
    return (j & ~15) + (((s & 7) >> 1) << 2) + (s & 1) + (((s >> 3) & 1) << 1);
}

// ---------------------------------------------------------------------------
// Prep: convert s (kpos-permuted cols) + weights (plain) to tf32 bits.
// ---------------------------------------------------------------------------
__global__ __launch_bounds__(256) void cvt_prep_kernel(
    const float* __restrict__ s,    const float* __restrict__ w_q,
    const float* __restrict__ w_kv, const float* __restrict__ w_vp,
    const float* __restrict__ w_out)
{
    const int i = blockIdx.x * 256 + threadIdx.x;
    if (i < 196608) {
        // s: scatter into kpos-permuted columns (float4 covers logical r..r+3,
        // r = base&7 in {0,4}; kpos8(r+j) = 2j + (r>>2))
        const size_t base = (size_t)i << 2;
        float4 v = *(const float4*)(s + base);
        float* d = g_s + (base & ~(size_t)7);
        const int o = ((int)base & 7) >> 2;   // 0 or 1
        d[o]     = __uint_as_float(f2tf32(v.x));
        d[o + 2] = __uint_as_float(f2tf32(v.y));
        d[o + 4] = __uint_as_float(f2tf32(v.z));
        d[o + 6] = __uint_as_float(f2tf32(v.w));
        return;
    }
    const float* src; float* dst; int off;
    if (i < 294912)      { src = w_q;   dst = g_wq;   off = i - 196608; }
    else if (i < 491520) { src = w_kv;  dst = g_wkv;  off = i - 294912; }
    else if (i < 528384) { src = w_vp;  dst = g_wvp;  off = i - 491520; }
    else                 { src = w_out; dst = g_wout; off = i - 528384; }
    float4 v = *(const float4*)(src + ((size_t)off << 2));
    float4 o = make_float4(__uint_as_float(f2tf32(v.x)), __uint_as_float(f2tf32(v.y)),
                           __uint_as_float(f2tf32(v.z)), __uint_as_float(f2tf32(v.w)));
    *(float4*)(dst + ((size_t)off << 2)) = o;
}

// ---------------------------------------------------------------------------
// cp.async double-buffered tf32 mainloop. A is kpos-permuted (LDS.64 frags);
// B plain. As stride 24 (conflict-free LDS.64), Bs stride 136.
// ---------------------------------------------------------------------------
template<int MT>
struct __align__(16) Tiles { float As[2][MT][24]; float Bs[2][16][136]; };

template<int MT>
__device__ __forceinline__ void gemm_mainloop(
    const float* __restrict__ A, int lda, const float* __restrict__ Bw,
    int K, int ldb, int m0, int n0,
    Tiles<MT>* t, float acc[MT / 32][4][4])
{
    const int tid = threadIdx.x;
    const int wid = tid >> 5, lane = tid & 31;
    const int wm = wid >> 2, wn = wid & 3;
    const int g = lane >> 2, tg = lane & 3;
    constexpr int RT = MT / 32;

#pragma unroll
    for (int mt = 0; mt < RT; mt++)
#pragma unroll
        for (int nt = 0; nt < 4; nt++)
#pragma unroll
            for (int i = 0; i < 4; i++) acc[mt][nt][i] = 0.f;

    const int nc = K >> 4;

    {
#pragma unroll
        for (int r = 0; r < MT / 64; r++) {
            const int idx = tid + (r << 8);
            const int rr = idx >> 2, cc = (idx & 3) << 2;
            cp16(&t->As[0][rr][cc], &A[(size_t)(m0 + rr) * lda + cc]);
        }
#pragma unroll
        for (int r = 0; r < 2; r++) {
            const int idx = tid + (r << 8);
            const int rr = idx >> 5, cc = (idx & 31) << 2;
            cp16(&t->Bs[0][rr][cc], &Bw[(size_t)rr * ldb + n0 + cc]);
        }
        CP_COMMIT();
    }

    for (int c = 0; c < nc; c++) {
        const int s = c & 1;
        if (c + 1 < nc) {
            const int k1 = (c + 1) << 4;
            const int s1 = s ^ 1;
#pragma unroll
            for (int r = 0; r < MT / 64; r++) {
                const int idx = tid + (r << 8);
                const int rr = idx >> 2, cc = (idx & 3) << 2;
                cp16(&t->As[s1][rr][cc], &A[(size_t)(m0 + rr) * lda + k1 + cc]);
            }
#pragma unroll
            for (int r = 0; r < 2; r++) {
                const int idx = tid + (r << 8);
                const int rr = idx >> 5, cc = (idx & 31) << 2;
                cp16(&t->Bs[s1][rr][cc], &Bw[(size_t)(k1 + rr) * ldb + n0 + cc]);
            }
            CP_COMMIT();
            CP_WAIT1();
        } else {
            CP_WAIT0();
        }
        __syncthreads();

#pragma unroll
        for (int ks = 0; ks < 2; ks++) {
            const int kc = (ks << 3) + tg;           // logical (B side)
            const int kp = (ks << 3) + (tg << 1);    // permuted pair base (A)
            uint32_t af[RT][4];
#pragma unroll
            for (int mt = 0; mt < RT; mt++) {
                const int mr = wm * (MT / 2) + (mt << 4) + g;
                float2 ta = *(const float2*)&t->As[s][mr    ][kp];
                float2 tb = *(const float2*)&t->As[s][mr + 8][kp];
                af[mt][0] = __float_as_uint(ta.x);
                af[mt][2] = __float_as_uint(ta.y);
                af[mt][1] = __float_as_uint(tb.x);
                af[mt][3] = __float_as_uint(tb.y);
            }
            uint32_t bf[4][2];
#pragma unroll
            for (int nt = 0; nt < 4; nt++) {
                const int bc = (wn << 5) + (nt << 3) + g;
                bf[nt][0] = __float_as_uint(t->Bs[s][kc    ][bc]);
                bf[nt][1] = __float_as_uint(t->Bs[s][kc + 4][bc]);
            }
#pragma unroll
            for (int mt = 0; mt < RT; mt++)
#pragma unroll
                for (int nt = 0; nt < 4; nt++)
                    mma_tf32(acc[mt][nt], af[mt][0], af[mt][1], af[mt][2], af[mt][3],
                             bf[nt][0], bf[nt][1]);
        }
        __syncthreads();
    }
}

// ---------------------------------------------------------------------------
// Fused projection GEMM (A = permuted g_s). Outputs as before.
// ---------------------------------------------------------------------------
__global__ __launch_bounds__(256) void proj_gemm_kernel(
    const float* __restrict__ b_q, const float* __restrict__ b_kv,
    const float* __restrict__ b_vp)
{
    __shared__ Tiles<128> t;
    const int bx = blockIdx.x;
    const int m0 = blockIdx.y << 7;

    const float* Bw; const float* bias; int ldb, n0, region;
    if (bx < 8)       { Bw = g_wq;  bias = b_q;  ldb = 1024; n0 = bx << 7;        region = 0; }
    else if (bx < 24) { Bw = g_wkv; bias = b_kv; ldb = 2048; n0 = (bx - 8) << 7;  region = 1; }
    else              { Bw = g_wvp; bias = b_vp; ldb = 384;  n0 = (bx - 24) << 7; region = 2; }

    float acc[4][4][4];
    gemm_mainloop<128>(g_s, 384, Bw, 384, ldb, m0, n0, &t, acc);

    const int tid = threadIdx.x;
    const int wid = tid >> 5, lane = tid & 31;
    const int wm = wid >> 2, wn = wid & 3;
    const int g = lane >> 2, tg = lane & 3;
    // 2*sqrt(1/(3*64)) * log2(e)  (exp2-domain softmax)
    const float sc2 = 0.14433756729740645f * 1.4426950408889634f;

#pragma unroll
    for (int mt = 0; mt < 4; mt++) {
        const int row0 = m0 + (wm << 6) + (mt << 4) + g;
#pragma unroll
        for (int nt = 0; nt < 4; nt++) {
            const int col = n0 + (wn << 5) + (nt << 3) + (tg << 1);
            const float b0 = bias[col], b1 = bias[col + 1];
#pragma unroll
            for (int half = 0; half < 2; half++) {
                const int row = row0 + half * 8;
                float2 v = make_float2(acc[mt][nt][half * 2]     + b0,
                                       acc[mt][nt][half * 2 + 1] + b1);
                const int b = row >> 10, n = row & 1023;
                if (region == 0) {
                    const int h = col >> 6, c = col & 63;
                    float* q = g_q + (size_t)(((b * NH + h) * NSEQ) + n) * HD;
                    const int p0 = kpos(c);                 // kpos(c+1) == p0+2
                    q[p0]     = __uint_as_float(f2tf32(v.x * sc2));
                    q[p0 + 2] = __uint_as_float(f2tf32(v.y * sc2));
                } else if (region == 1) {
                    const int h = col >> 7, r = col & 127;
                    if (r < 64) {
                        float* k = g_k + (size_t)(((b * NH + h) * NSEQ) + n) * HD;
                        const int p0 = kpos(r);
                        k[p0]     = __uint_as_float(f2tf32(v.x));
                        k[p0 + 2] = __uint_as_float(f2tf32(v.y));
                    } else {
                        __nv_bfloat16* vb = g_vb +
                            ((size_t)((b * NH + h) * DVV + (r - 64)) * NSEQ) + jp(n);
                        vb[0]    = __float2bfloat16(v.x);
                        vb[NSEQ] = __float2bfloat16(v.y);
                    }
                } else {
                    *(float2*)&g_vpout[(size_t)row * 384 + col] = v;
                }
            }
        }
    }
}

// ---------------------------------------------------------------------------
// Output GEMM, split-K, MT=64 tiles, A = permuted g_cat: grid (3,32,KSPLIT).
// ---------------------------------------------------------------------------
__global__ __launch_bounds__(256) void out_gemm_kernel()
{
    __shared__ Tiles<64> t;
    const int m0 = blockIdx.y << 6;
    const int n0 = blockIdx.x << 7;
    const int z  = blockIdx.z;
    const int koff = z * (CATD / KSPLIT);

    float acc[2][4][4];
    gemm_mainloop<64>(g_cat + koff, CATD, g_wout + (size_t)koff * 384,
                      CATD / KSPLIT, 384, m0, n0, &t, acc);

    const int tid = threadIdx.x;
    const int wid = tid >> 5, lane = tid & 31;
    const int wm = wid >> 2, wn = wid & 3;
    const int g = lane >> 2, tg = lane & 3;
    float* dst = g_opart[z];

#pragma unroll
    for (int mt = 0; mt < 2; mt++) {
        const int row = m0 + (wm << 5) + (mt << 4) + g;
#pragma unroll
        for (int nt = 0; nt < 4; nt++) {
            const int col = n0 + (wn << 5) + (nt << 3) + (tg << 1);
            *(float2*)&dst[(size_t)row * 384 + col] =
                make_float2(acc[mt][nt][0], acc[mt][nt][1]);
            *(float2*)&dst[(size_t)(row + 8) * 384 + col] =
                make_float2(acc[mt][nt][2], acc[mt][nt][3]);
        }
    }
}

__global__ __launch_bounds__(256) void out_reduce_kernel(
    const float* __restrict__ b_out, float* __restrict__ out)
{
    const int idx = blockIdx.x * 256 + threadIdx.x;
    const int col = (idx << 2) % 384;
    float4 r = *(const float4*)&b_out[col];
#pragma unroll
    for (int z = 0; z < KSPLIT; z++) {
        float4 p = *(const float4*)&g_opart[z][idx << 2];
        r.x += p.x; r.y += p.y; r.z += p.z; r.w += p.w;
    }
    *(float4*)&out[idx << 2] = r;
}

// ---------------------------------------------------------------------------
// vp rotation: global frame -> bf16 transposed (j-permuted) g_vb rows 64..87.
// ---------------------------------------------------------------------------
__global__ void vp_rearrange_kernel(const float* __restrict__ rot,
                                    const float* __restrict__ trans) {
    const int row = blockIdx.x;
    const int b = row >> 10, n = row & 1023;
    const int t = threadIdx.x;
    const float* pr = g_vpout + (size_t)row * 384;
    const float* R = rot + row * 9;
    const float* T = trans + row * 3;
    const float x = pr[t];
    const float y = pr[128 + t];
    const float z = pr[256 + t];
    const float gx = R[0]*x + R[1]*y + R[2]*z + T[0];
    const float gy = R[3]*x + R[4]*y + R[5]*z + T[1];
    const float gz = R[6]*x + R[7]*y + R[8]*z + T[2];
    const int h = t >> 3, pp = t & 7;
    __nv_bfloat16* vb = g_vb +
        ((size_t)((b * NH + h) * DVV + 64 + pp * 3) * NSEQ) + jp(n);
    vb[0]        = __float2bfloat16(gx);
    vb[NSEQ]     = __float2bfloat16(gy);
    vb[2 * NSEQ] = __float2bfloat16(gz);
}

// ---------------------------------------------------------------------------
// Flash attention (unchanged mainloop from R16 best) with g_cat epilogue
// writes now kpos-permuted to match the out GEMM's A layout.
// ---------------------------------------------------------------------------
#define KS_STRIDE 72
#define VT_STRIDE 80
#define TILEF (64 * KS_STRIDE + (DVV * VT_STRIDE) / 2)   // floats: 4608 + 3520
#define ATT_SMEM (2 * TILEF * 4)                          // 65024 bytes

__global__ __launch_bounds__(256, 2) void attn_mma_kernel(
    const float* __restrict__ mask, const float* __restrict__ rot,
    const float* __restrict__ trans)
{
    extern __shared__ float smem_dyn[];
    __shared__ float msk2[2][64];
    float (*sp)[25] = (float(*)[25])smem_dyn;      // epilogue alias

    const int b = blockIdx.z, h = blockIdx.y;
    const int i0 = blockIdx.x << 7;
    const int tid = threadIdx.x;
    const int wid = tid >> 5, lane = tid & 31;
    const int g = lane >> 2, tg = lane & 3;
    const int wrow = wid << 4;

    const float* qbase = g_q + (size_t)((b * NH + h) * NSEQ) * HD;
    const float* kbase = g_k + (size_t)((b * NH + h) * NSEQ) * HD;
    const __nv_bfloat16* vbbase = g_vb + (size_t)(b * NH + h) * DVV * NSEQ;

    // Q fragments: permuted layout -> (a0,a2) and (a1,a3) are float2 loads
    uint32_t qa[8][4];
    {
        const float* q0 = qbase + (size_t)(i0 + wrow + g) * HD;
        const float* q1 = qbase + (size_t)(i0 + wrow + g + 8) * HD;
#pragma unroll
        for (int kt = 0; kt < 8; kt++) {
            float2 t0 = *(const float2*)&q0[(kt << 3) + (tg << 1)];
            float2 t1 = *(const float2*)&q1[(kt << 3) + (tg << 1)];
            qa[kt][0] = __float_as_uint(t0.x);
            qa[kt][2] = __float_as_uint(t0.y);
            qa[kt][1] = __float_as_uint(t1.x);
            qa[kt][3] = __float_as_uint(t1.y);
        }
    }
    const float CLOG = 144269.50408889634f;   // 1e5 * log2(e)
    const float A0 = CLOG * mask[b * NSEQ + i0 + wrow + g];
    const float A1 = CLOG * mask[b * NSEQ + i0 + wrow + g + 8];

    float l0 = 0.f, l1 = 0.f;
    float acc[11][4];
#pragma unroll
    for (int nt = 0; nt < 11; nt++)
#pragma unroll
        for (int i = 0; i < 4; i++) acc[nt][i] = 0.f;

    auto stage_tile = [&](int j0, int s) {
        float* buf = smem_dyn + s * TILEF;
        float (*ksb)[KS_STRIDE] = (float(*)[KS_STRIDE])buf;
        uint16_t* vtb = (uint16_t*)(buf + 64 * KS_STRIDE);
#pragma unroll
        for (int r = 0; r < 4; r++) {                   // ks: 64 rows x 16 segs
            const int task = tid + (r << 8);
            const int rr = task >> 4, seg = task & 15;
            cp16(&ksb[rr][seg << 2], &kbase[(size_t)(j0 + rr) * HD + (seg << 2)]);
        }
#pragma unroll
        for (int r = 0; r < 2; r++) {                   // vsT: 88 rows x 8 segs
            const int task = tid + (r << 8);
            const int d = task >> 3, seg = task & 7;
            cp16(vtb + d * VT_STRIDE + (seg << 3),
                 vbbase + (size_t)d * NSEQ + j0 + (seg << 3));
        }
        if (tid < 192) {
            const int task = tid + 512;
            const int d = task >> 3, seg = task & 7;
            cp16(vtb + d * VT_STRIDE + (seg << 3),
                 vbbase + (size_t)d * NSEQ + j0 + (seg << 3));
        }
        if (tid < 16) cp16(&msk2[s][tid << 2], &mask[b * NSEQ + j0 + (tid << 2)]);
    };

    stage_tile(0, 0);
    CP_COMMIT();

    for (int jt = 0; jt < 16; jt++) {
        const int s = jt & 1;
        if (jt + 1 < 16) {
            stage_tile((jt + 1) << 6, s ^ 1);
            CP_COMMIT();
            CP_WAIT1();
        } else {
            CP_WAIT0();
        }
        __syncthreads();

        float* buf = smem_dyn + s * TILEF;
        float (*ks)[KS_STRIDE] = (float(*)[KS_STRIDE])buf;
        const uint16_t* vsT = (const uint16_t*)(buf + 64 * KS_STRIDE);
        const float* msk = msk2[s];

        // S' = (log2e * logits) via tf32 mma; B-frags as single LDS.64
        float sc[8][4];
#pragma unroll
        for (int nt = 0; nt < 8; nt++)
#pragma unroll
            for (int i = 0; i < 4; i++) sc[nt][i] = 0.f;
#pragma unroll
        for (int kt = 0; kt < 8; kt++) {
#pragma unroll
            for (int nt = 0; nt < 8; nt++) {
                float2 bb = *(const float2*)&ks[(nt << 3) + g][(kt << 3) + (tg << 1)];
                mma_tf32(sc[nt], qa[kt][0], qa[kt][1], qa[kt][2], qa[kt][3],
                         __float_as_uint(bb.x), __float_as_uint(bb.y));
            }
        }

        // p = 2^(sc + A*mc - C); row sums; p overwrites sc
        float ps0 = 0.f, ps1 = 0.f;
#pragma unroll
        for (int nt = 0; nt < 8; nt++) {
            const float mc0 = msk[(nt << 3) + (tg << 1)];
            const float mc1 = msk[(nt << 3) + (tg << 1) + 1];
            sc[nt][0] = ex2f(sc[nt][0] + A0 * mc0 - CLOG);
            sc[nt][1] = ex2f(sc[nt][1] + A0 * mc1 - CLOG);
            sc[nt][2] = ex2f(sc[nt][2] + A1 * mc0 - CLOG);
            sc[nt][3] = ex2f(sc[nt][3] + A1 * mc1 - CLOG);
            ps0 += sc[nt][0] + sc[nt][1];
            ps1 += sc[nt][2] + sc[nt][3];
        }
        ps0 += __shfl_xor_sync(0xffffffffu, ps0, 1);
        ps0 += __shfl_xor_sync(0xffffffffu, ps0, 2);
        ps1 += __shfl_xor_sync(0xffffffffu, ps1, 1);
        ps1 += __shfl_xor_sync(0xffffffffu, ps1, 2);
        l0 += ps0;
        l1 += ps1;

        // O += P * V : 4 k16-groups x 11 n-tiles; b0|b1 = one LDS.64
#pragma unroll
        for (int m = 0; m < 4; m++) {
            uint32_t a0 = pack_bf16(sc[2*m][0],     sc[2*m][1]);
            uint32_t a1 = pack_bf16(sc[2*m][2],     sc[2*m][3]);
            uint32_t a2 = pack_bf16(sc[2*m + 1][0], sc[2*m + 1][1]);
            uint32_t a3 = pack_bf16(sc[2*m + 1][2], sc[2*m + 1][3]);
#pragma unroll
            for (int nt = 0; nt < 11; nt++) {
                const int hoff = ((nt << 3) + g) * VT_STRIDE + (m << 4) + (tg << 2);
                uint2 bb = *(const uint2*)(vsT + hoff);
                mma_bf16(acc[nt], a0, a1, a2, a3, bb.x, bb.y);
            }
        }
        __syncthreads();
    }

    const float inv0 = 1.0f / l0;
    const float inv1 = 1.0f / l1;
    const int lr0 = wrow + g, lr1 = wrow + g + 8;

    // v dims: to g_cat as tf32 bits, kpos-permuted columns
    {
        float* cr0 = g_cat + (size_t)(b * NSEQ + i0 + lr0) * CATD + h * 64;
        float* cr1 = g_cat + (size_t)(b * NSEQ + i0 + lr1) * CATD + h * 64;
#pragma unroll
        for (int nt = 0; nt < 8; nt++) {
            const int col = (nt << 3) + (tg << 1);     // logical (aligned to 8-blk)
            const int cb = col & ~7;
            const int pA = cb + kpos8(col & 7);
            const int pB = cb + kpos8((col & 7) + 1);
            cr0[pA] = __uint_as_float(f2tf32(acc[nt][0] * inv0));
            cr0[pB] = __uint_as_float(f2tf32(acc[nt][1] * inv0));
            cr1[pA] = __uint_as_float(f2tf32(acc[nt][2] * inv1));
            cr1[pB] = __uint_as_float(f2tf32(acc[nt][3] * inv1));
        }
    }
    // pt dims: stage normalized (fp32) into sp (aliases dead tile storage)
#pragma unroll
    for (int nt = 8; nt < 11; nt++) {
        const int c = ((nt - 8) << 3) + (tg << 1);
        sp[lr0][c]     = acc[nt][0] * inv0;
        sp[lr0][c + 1] = acc[nt][1] * inv0;
        sp[lr1][c]     = acc[nt][2] * inv1;
        sp[lr1][c + 1] = acc[nt][3] * inv1;
    }
    __syncthreads();

    for (int task = tid; task < 1024; task += 256) {
        const int lr = task >> 3, p2 = task & 7;
        const int grow = b * NSEQ + i0 + lr;
        const float* R = rot + (size_t)grow * 9;
        const float* T = trans + (size_t)grow * 3;
        const float dx = sp[lr][p2 * 3 + 0] - T[0];
        const float dy = sp[lr][p2 * 3 + 1] - T[1];
        const float dz = sp[lr][p2 * 3 + 2] - T[2];
        const float lx = R[0] * dx + R[3] * dy + R[6] * dz;
        const float ly = R[1] * dx + R[4] * dy + R[7] * dz;
        const float lz = R[2] * dx + R[5] * dy + R[8] * dz;
        float* cr = g_cat + (size_t)grow * CATD;
        const int pcol = h * 8 + kpos8(p2);   // h*8 is 8-block aligned
        cr[1024 + pcol] = __uint_as_float(f2tf32(lx));
        cr[1152 + pcol] = __uint_as_float(f2tf32(ly));
        cr[1280 + pcol] = __uint_as_float(f2tf32(lz));
        cr[1408 + pcol] = __uint_as_float(f2tf32(sqrtf(lx*lx + ly*ly + lz*lz + 1e-8f)));
    }
}

// ---------------------------------------------------------------------------
extern "C" void kernel_launch(void* const* d_in, const int* in_sizes, int n_in,
                              void* d_out, int out_size) {
    const float* s     = (const float*)d_in[0];
    // d_in[1] = z : unused by the reference -> never read
    const float* rot   = (const float*)d_in[2];
    const float* trans = (const float*)d_in[3];
    const float* mask  = (const float*)d_in[4];
    const float* w_q   = (const float*)d_in[5];
    const float* b_q   = (const float*)d_in[6];
    const float* w_kv  = (const float*)d_in[7];
    const float* b_kv  = (const float*)d_in[8];
    const float* w_vp  = (const float*)d_in[9];
    const float* b_vp  = (const float*)d_in[10];
    const float* w_out = (const float*)d_in[11];
    const float* b_out = (const float*)d_in[12];
    float* out = (float*)d_out;

    cudaFuncSetAttribute(attn_mma_kernel,
                         cudaFuncAttributeMaxDynamicSharedMemorySize, ATT_SMEM);

    // Convert s (kpos cols) + weights to tf32 bits (streaming)
    cvt_prep_kernel<<<2640, 256>>>(s, w_q, w_kv, w_vp, w_out);

    // Fused projections (q|kv|vp)
    proj_gemm_kernel<<<dim3(27, 16), 256>>>(b_q, b_kv, b_vp);

    // vp rotation to global frame (bf16 transposed, j-permuted output)
    vp_rearrange_kernel<<<NTOK, 128>>>(rot, trans);

    // Tensor-core flash attention with fused (permuted) cat epilogue
    attn_mma_kernel<<<dim3(8, NH, NB), 256, ATT_SMEM>>>(mask, rot, trans);

    // Output projection: split-K partials (MT=64, 384 CTAs) + reduce
    out_gemm_kernel<<<dim3(3, 32, KSPLIT), 256>>>();
    out_reduce_kernel<<<NTOK * 384 / 4 / 256, 256>>>(b_out, out);
}